// round 10
// baseline (speedup 1.0000x reference)
#include <cuda_runtime.h>
#include <cuda_bf16.h>
#include <math.h>

#define HWSZ   19200
#define IMW    160
#define NPIX   2400
#define NBLKX  75          // 19200 / 256 cell blocks
#define NCOBJ  7           // object classes 1..7

typedef unsigned long long ull;

// ---------------- packed f32x2 helpers ----------------
__device__ __forceinline__ ull pk2(float lo, float hi) {
    ull r; asm("mov.b64 %0, {%1, %2};" : "=l"(r) : "f"(lo), "f"(hi)); return r;
}
__device__ __forceinline__ void up2(ull v, float& lo, float& hi) {
    asm("mov.b64 {%0, %1}, %2;" : "=f"(lo), "=f"(hi) : "l"(v));
}
__device__ __forceinline__ ull add2(ull a, ull b) {
    ull r; asm("add.rn.f32x2 %0, %1, %2;" : "=l"(r) : "l"(a), "l"(b)); return r;
}
__device__ __forceinline__ ull mul2(ull a, ull b) {
    ull r; asm("mul.rn.f32x2 %0, %1, %2;" : "=l"(r) : "l"(a), "l"(b)); return r;
}
__device__ __forceinline__ ull fma2(ull a, ull b, ull c) {
    ull r; asm("fma.rn.f32x2 %0, %1, %2, %3;" : "=l"(r) : "l"(a), "l"(b), "l"(c)); return r;
}

// ---------------- scratch ----------------
// pair p of class c: g_xy[c][4p..4p+3] = (-xs0,-xs1,-ys0,-ys1)
//                    g_nn[c][4p..4p+3] = (nx'0,nx'1,ny'0,ny'1)   nx' = nx/0.9
//                    g_dp[c][2p..2p+1] = (dep0, dep1)
__device__ __align__(16) float g_xy[NCOBJ][4800];
__device__ __align__(16) float g_nn[NCOBJ][4800];
__device__ __align__(8)  float g_dp[NCOBJ][2400];
__device__ int   g_cnt[NCOBJ];
__device__ int   g_npair[NCOBJ];
__device__ int   g_pv[NCOBJ * NBLKX];
__device__ int   g_pl[NCOBJ * NBLKX];
__device__ float g_pds[NCOBJ * NBLKX];
__device__ unsigned g_ctr = 0;                   // arrival counter (self-resetting)

struct P4 { ull a, b; };

// ============================================================================
// Kernel 1: prep — one 1024-thread block; batched loads -> SMEM staging ->
// warp-per-class ballot compaction from SMEM
// ============================================================================
__global__ void __launch_bounds__(1024) prep_kernel(const int* __restrict__ labels,
                                                    const int* __restrict__ masks,
                                                    const float* __restrict__ vp)
{
    // s_rec[i] = { xy packed as 2xu16 in float bits, nx', ny', dep }
    __shared__ __align__(16) float4 s_rec[NPIX];   // 38400 B
    __shared__ int s_cls[NPIX];                    //  9600 B

    const int tid = threadIdx.x, lane = tid & 31, warp = tid >> 5;

    int labv[3], mskv[3];
    #pragma unroll
    for (int k = 0; k < 3; k++) {
        int i = k * 1024 + tid;
        labv[k] = (i < NPIX) ? labels[i * 8] : 0;
    }
    #pragma unroll
    for (int k = 0; k < 3; k++) {
        int i = k * 1024 + tid;
        mskv[k] = (i < NPIX) ? masks[i * 8] : 0;
    }
    #pragma unroll
    for (int k = 0; k < 3; k++) {
        int i = k * 1024 + tid;
        if (i < NPIX) {
            const int c = (mskv[k] > 0 && labv[k] > 0) ? labv[k] : 0;
            s_cls[i] = c;
            if (c) {
                const int idx = i * 8;
                const float vx = vp[(c * 3 + 0) * HWSZ + idx];
                const float vy = vp[(c * 3 + 1) * HWSZ + idx];
                const float vz = vp[(c * 3 + 2) * HWSZ + idx];
                const float nrm = sqrtf(vx * vx + vy * vy) + 1e-6f;
                const float nxp = (vx / nrm) * (1.0f / 0.9f);
                const float nyp = (vy / nrm) * (1.0f / 0.9f);
                const unsigned xs = (unsigned)(idx % IMW);
                const unsigned ys = (unsigned)(idx / IMW);
                s_rec[i] = make_float4(__uint_as_float(xs | (ys << 16)), nxp, nyp, expf(vz));
            }
        }
    }
    __syncthreads();

    if (warp < NCOBJ) {
        const int myc = warp + 1;
        const unsigned below = (1u << lane) - 1u;
        int base = 0;
        #pragma unroll 5
        for (int it = 0; it < 75; it++) {
            const int i = it * 32 + lane;
            const bool pred = (s_cls[i] == myc);
            const unsigned bal = __ballot_sync(0xFFFFFFFFu, pred);
            if (pred) {
                const float4 r = s_rec[i];
                const unsigned xy = __float_as_uint(r.x);
                const float xs = (float)(xy & 0xFFFFu);
                const float ys = (float)(xy >> 16);
                const int slot = base + __popc(bal & below);
                const int p = slot >> 1, h = slot & 1;
                g_xy[warp][p * 4 + h]     = -xs;
                g_xy[warp][p * 4 + 2 + h] = -ys;
                g_nn[warp][p * 4 + h]     = r.y;
                g_nn[warp][p * 4 + 2 + h] = r.z;
                g_dp[warp][p * 2 + h]     = r.w;
            }
            base += __popc(bal);
        }
        const int pad = (base + 7) & ~7;      // never-inlier dummies (n'=0 -> dot=0)
        for (int s = base + lane; s < pad; s += 32) {
            const int p = s >> 1, h = s & 1;
            g_xy[warp][p * 4 + h] = 0.f;  g_xy[warp][p * 4 + 2 + h] = 0.f;
            g_nn[warp][p * 4 + h] = 0.f;  g_nn[warp][p * 4 + 2 + h] = 0.f;
            g_dp[warp][p * 2 + h] = 0.f;
        }
        if (lane == 0) { g_cnt[warp] = base; g_npair[warp] = pad >> 1; }
    }
}

// ============================================================================
// Kernel 2: vote — 512 threads/block: 256 cells x 2 in-block pixel halves.
// Combine halves in SMEM, block argmax, last-arriving block does final outputs.
// ============================================================================
__global__ void __launch_bounds__(512, 4) vote_final_kernel(const float* __restrict__ extents,
                                                            const float* __restrict__ poses,
                                                            const float* __restrict__ meta,
                                                            float* __restrict__ out)
{
    __shared__ __align__(16) P4     s_xy[1200];   // 19200 B
    __shared__ __align__(16) P4     s_nn[1200];   // 19200 B
    __shared__ __align__(16) float2 s_dp[1200];   //  9600 B  (total 48000)
    __shared__ unsigned s_old;

    const int cls  = blockIdx.y;           // 0..6 (class cls+1)
    const int bx   = blockIdx.x;           // 0..74
    const int tid  = threadIdx.x;          // 0..511
    const int cell = tid & 255;
    const int half = tid >> 8;             // 0 or 1
    const int lane = tid & 31, warp = tid >> 5;

    const int npair = g_npair[cls];        // multiple of 4

    const P4*     gxy = (const P4*)g_xy[cls];
    const P4*     gnn = (const P4*)g_nn[cls];
    const float2* gdp = (const float2*)g_dp[cls];
    for (int i = tid; i < npair; i += 512) { s_xy[i] = gxy[i]; s_nn[i] = gnn[i]; s_dp[i] = gdp[i]; }
    __syncthreads();

    const int loc = bx * 256 + cell;
    const float gx = (float)(loc % IMW);
    const float gy = (float)(loc / IMW);
    const ull gx2 = pk2(gx, gx);
    const ull gy2 = pk2(gy, gy);

    const int p0 = half ? (npair >> 1) : 0;
    const int p1 = half ? npair : (npair >> 1);

    int v = 0; float ds = 0.f;
    #pragma unroll 2
    for (int p = p0; p < p1; p++) {
        P4 axy = s_xy[p];
        P4 ann = s_nn[p];
        float2 dd = s_dp[p];
        ull dx2  = add2(gx2, axy.a);
        ull dy2  = add2(gy2, axy.b);
        ull dot2 = fma2(dy2, ann.b, mul2(dx2, ann.a));   // dot' = dot/0.9
        ull d22  = fma2(dy2, dy2, mul2(dx2, dx2));       // d2
        ull q2   = mul2(dot2, dot2);
        float dot0, dot1, q0, q1, e0, e1;
        up2(dot2, dot0, dot1); up2(q2, q0, q1); up2(d22, e0, e1);
        if (dot0 > 0.f && q0 > e0) { v++; ds += dd.x; }
        if (dot1 > 0.f && q1 > e1) { v++; ds += dd.y; }
    }

    // ---- combine halves + block argmax (max count, min loc) in SMEM ----
    __syncthreads();
    int*   rv = (int*)s_xy;       // 512 ints
    float* rd = (float*)s_nn;     // 512 floats
    int*   rl = (int*)s_dp;       // 256 ints
    rv[tid] = v; rd[tid] = ds;
    __syncthreads();
    if (tid < 256) {
        rv[tid] = rv[tid] + rv[tid + 256];          // half0 + half1 (fixed order)
        rd[tid] = rd[tid] + rd[tid + 256];
        rl[tid] = loc;
    }
    __syncthreads();
    #pragma unroll
    for (int s = 128; s > 0; s >>= 1) {
        if (tid < s) {
            int ov = rv[tid + s], ol = rl[tid + s];
            if (ov > rv[tid] || (ov == rv[tid] && ol < rl[tid])) {
                rv[tid] = ov; rl[tid] = ol; rd[tid] = rd[tid + s];
            }
        }
        __syncthreads();
    }
    if (tid == 0) {
        g_pv [cls * NBLKX + bx] = rv[0];
        g_pl [cls * NBLKX + bx] = rl[0];
        g_pds[cls * NBLKX + bx] = rd[0];
    }

    // ---- arrival: last block performs final reduction + outputs ----
    __threadfence();
    __syncthreads();
    if (tid == 0) s_old = atomicAdd(&g_ctr, 1u);
    __syncthreads();
    if (s_old != (unsigned)(NBLKX * NCOBJ) - 1u) return;
    __threadfence();

    // warp c handles class c (0..7); class 0 never votes -> zeros path
    const int c = warp;
    if (c < 8) {
        float vmax = 0.f, dsum = 0.f, nv = 0.f;
        int best = 0;
        if (c > 0) {
            const int ci = c - 1;
            int bc = -1, bl = 0; float bd = 0.f;
            for (int j = lane; j < NBLKX; j += 32) {
                int   vv = g_pv [ci * NBLKX + j];
                int   ll = g_pl [ci * NBLKX + j];
                float dd = g_pds[ci * NBLKX + j];
                if (vv > bc || (vv == bc && ll < bl)) { bc = vv; bl = ll; bd = dd; }
            }
            #pragma unroll
            for (int off = 16; off > 0; off >>= 1) {
                int   ov = __shfl_down_sync(0xFFFFFFFFu, bc, off);
                int   ol = __shfl_down_sync(0xFFFFFFFFu, bl, off);
                float od = __shfl_down_sync(0xFFFFFFFFu, bd, off);
                if (ov > bc || (ov == bc && ol < bl)) { bc = ov; bl = ol; bd = od; }
            }
            vmax = (float)bc; best = bl; dsum = bd;
            nv = (float)g_cnt[ci];
        }

        if (lane == 0) {
            const float dbar = dsum / fmaxf(vmax, 1.f);
            const float cx = (float)(best % IMW);
            const float cy = (float)(best / IMW);
            const float fx = meta[0], px = meta[2], fy = meta[4], py = meta[5];
            const float e0 = extents[c * 3 + 0];
            const float e1 = extents[c * 3 + 1];
            const float e2 = extents[c * 3 + 2];
            const float diag = sqrtf(e0 * e0 + e1 * e1 + e2 * e2);
            const float safe = fmaxf(dbar, 1e-6f);
            const float bw = diag * fx / safe;
            const float bh = diag * fy / safe;
            const float score = vmax / fmaxf(nv, 1.f);

            float* box = out + c * 7;
            box[0] = 0.f;
            box[1] = (float)c;
            box[2] = cx - bw * 0.5f;
            box[3] = cy - bh * 0.5f;
            box[4] = cx + bw * 0.5f;
            box[5] = cy + bh * 0.5f;
            box[6] = score;

            float* pp = out + 56 + c * 7;
            pp[0] = poses[c * 7 + 0];
            pp[1] = poses[c * 7 + 1];
            pp[2] = poses[c * 7 + 2];
            pp[3] = poses[c * 7 + 3];
            pp[4] = (cx - px) * dbar / fmaxf(fx, 1e-6f);
            pp[5] = (cy - py) * dbar / fmaxf(fy, 1e-6f);
            pp[6] = dbar;
        }
    }
    if (tid == 0) g_ctr = 0;                  // reset for next replay
}

// ============================================================================
extern "C" void kernel_launch(void* const* d_in, const int* in_sizes, int n_in,
                              void* d_out, int out_size)
{
    const int*   labels  = (const int*)d_in[0];
    const int*   masks   = (const int*)d_in[1];
    const float* vp      = (const float*)d_in[2];
    const float* extents = (const float*)d_in[3];
    const float* poses   = (const float*)d_in[4];
    const float* meta    = (const float*)d_in[5];
    float* out = (float*)d_out;

    prep_kernel<<<1, 1024>>>(labels, masks, vp);
    vote_final_kernel<<<dim3(NBLKX, NCOBJ), 512>>>(extents, poses, meta, out);
}

// round 13
// speedup vs baseline: 1.1502x; 1.1502x over previous
#include <cuda_runtime.h>
#include <cuda_bf16.h>
#include <math.h>

#define HWSZ   19200
#define IMW    160
#define NPIX   2400
#define NBLKC  19          // 19 x 1024 cells = 19456 >= 19200
#define NCOBJ  7           // object classes 1..7

typedef unsigned long long ull;

// ---------------- packed f32x2 helpers ----------------
__device__ __forceinline__ ull pk2(float lo, float hi) {
    ull r; asm("mov.b64 %0, {%1, %2};" : "=l"(r) : "f"(lo), "f"(hi)); return r;
}
__device__ __forceinline__ void up2(ull v, float& lo, float& hi) {
    asm("mov.b64 {%0, %1}, %2;" : "=f"(lo), "=f"(hi) : "l"(v));
}
__device__ __forceinline__ ull add2(ull a, ull b) {
    ull r; asm("add.rn.f32x2 %0, %1, %2;" : "=l"(r) : "l"(a), "l"(b)); return r;
}
__device__ __forceinline__ ull mul2(ull a, ull b) {
    ull r; asm("mul.rn.f32x2 %0, %1, %2;" : "=l"(r) : "l"(a), "l"(b)); return r;
}
__device__ __forceinline__ ull fma2(ull a, ull b, ull c) {
    ull r; asm("fma.rn.f32x2 %0, %1, %2, %3;" : "=l"(r) : "l"(a), "l"(b), "l"(c)); return r;
}

// ---------------- scratch ----------------
// pair p of class c: g_xy[c][4p..4p+3] = (-xs0,-xs1,-ys0,-ys1)
//                    g_nn[c][4p..4p+3] = (nx'0,nx'1,ny'0,ny'1)   nx' = nx/0.9
//                    g_dp[c][2p..2p+1] = (dep0, dep1)
__device__ __align__(16) float g_xy[NCOBJ][4800];
__device__ __align__(16) float g_nn[NCOBJ][4800];
__device__ __align__(8)  float g_dp[NCOBJ][2400];
__device__ int   g_cnt[NCOBJ];
__device__ int   g_npair[NCOBJ];
__device__ float g_pv[NCOBJ * NBLKC];
__device__ int   g_pl[NCOBJ * NBLKC];
__device__ float g_pds[NCOBJ * NBLKC];
__device__ unsigned g_ctr = 0;                   // arrival counter (self-resetting)

struct P4 { ull a, b; };

// ============================================================================
// Kernel 1: prep — one 1024-thread block; batched loads -> SMEM staging ->
// warp-per-class ballot compaction from SMEM
// ============================================================================
__global__ void __launch_bounds__(1024) prep_kernel(const int* __restrict__ labels,
                                                    const int* __restrict__ masks,
                                                    const float* __restrict__ vp)
{
    // s_rec[i] = { xy packed as 2xu16 in float bits, nx', ny', dep }
    __shared__ __align__(16) float4 s_rec[NPIX];   // 38400 B
    __shared__ int s_cls[NPIX];                    //  9600 B

    const int tid = threadIdx.x, lane = tid & 31, warp = tid >> 5;

    int labv[3], mskv[3];
    #pragma unroll
    for (int k = 0; k < 3; k++) {
        int i = k * 1024 + tid;
        labv[k] = (i < NPIX) ? labels[i * 8] : 0;
    }
    #pragma unroll
    for (int k = 0; k < 3; k++) {
        int i = k * 1024 + tid;
        mskv[k] = (i < NPIX) ? masks[i * 8] : 0;
    }
    #pragma unroll
    for (int k = 0; k < 3; k++) {
        int i = k * 1024 + tid;
        if (i < NPIX) {
            const int c = (mskv[k] > 0 && labv[k] > 0) ? labv[k] : 0;
            s_cls[i] = c;
            if (c) {
                const int idx = i * 8;
                const float vx = vp[(c * 3 + 0) * HWSZ + idx];
                const float vy = vp[(c * 3 + 1) * HWSZ + idx];
                const float vz = vp[(c * 3 + 2) * HWSZ + idx];
                const float nrm = sqrtf(vx * vx + vy * vy) + 1e-6f;
                const float nxp = (vx / nrm) * (1.0f / 0.9f);
                const float nyp = (vy / nrm) * (1.0f / 0.9f);
                const unsigned xs = (unsigned)(idx % IMW);
                const unsigned ys = (unsigned)(idx / IMW);
                s_rec[i] = make_float4(__uint_as_float(xs | (ys << 16)), nxp, nyp, expf(vz));
            }
        }
    }
    __syncthreads();

    if (warp < NCOBJ) {
        const int myc = warp + 1;
        const unsigned below = (1u << lane) - 1u;
        int base = 0;
        #pragma unroll 5
        for (int it = 0; it < 75; it++) {
            const int i = it * 32 + lane;
            const bool pred = (s_cls[i] == myc);
            const unsigned bal = __ballot_sync(0xFFFFFFFFu, pred);
            if (pred) {
                const float4 r = s_rec[i];
                const unsigned xy = __float_as_uint(r.x);
                const float xs = (float)(xy & 0xFFFFu);
                const float ys = (float)(xy >> 16);
                const int slot = base + __popc(bal & below);
                const int p = slot >> 1, h = slot & 1;
                g_xy[warp][p * 4 + h]     = -xs;
                g_xy[warp][p * 4 + 2 + h] = -ys;
                g_nn[warp][p * 4 + h]     = r.y;
                g_nn[warp][p * 4 + 2 + h] = r.z;
                g_dp[warp][p * 2 + h]     = r.w;
            }
            base += __popc(bal);
        }
        const int pad = (base + 7) & ~7;      // never-inlier dummies (n'=0 -> dot=0)
        for (int s = base + lane; s < pad; s += 32) {
            const int p = s >> 1, h = s & 1;
            g_xy[warp][p * 4 + h] = 0.f;  g_xy[warp][p * 4 + 2 + h] = 0.f;
            g_nn[warp][p * 4 + h] = 0.f;  g_nn[warp][p * 4 + 2 + h] = 0.f;
            g_dp[warp][p * 2 + h] = 0.f;
        }
        if (lane == 0) { g_cnt[warp] = base; g_npair[warp] = pad >> 1; }
    }
}

// ============================================================================
// Kernel 2: vote — 512 threads/block, 2 cells/thread (1024 cells/block),
// grid (19, 7) = 133 blocks = one balanced wave. Shuffle-based block argmax.
// Last-arriving block does the final per-class reduction + outputs.
// ============================================================================
__global__ void __launch_bounds__(512) vote_final_kernel(const float* __restrict__ extents,
                                                         const float* __restrict__ poses,
                                                         const float* __restrict__ meta,
                                                         float* __restrict__ out)
{
    __shared__ __align__(16) P4     s_xy[1200];   // 19200 B
    __shared__ __align__(16) P4     s_nn[1200];   // 19200 B
    __shared__ __align__(16) float2 s_dp[1200];   //  9600 B
    __shared__ float s_wv[16];
    __shared__ int   s_wl[16];
    __shared__ float s_wd[16];
    __shared__ unsigned s_old;

    const int cls  = blockIdx.y;           // 0..6 (class cls+1)
    const int bx   = blockIdx.x;           // 0..18
    const int tid  = threadIdx.x;          // 0..511
    const int lane = tid & 31, warp = tid >> 5;

    const int npair = g_npair[cls];        // multiple of 4

    const P4*     gxy = (const P4*)g_xy[cls];
    const P4*     gnn = (const P4*)g_nn[cls];
    const float2* gdp = (const float2*)g_dp[cls];
    for (int i = tid; i < npair; i += 512) { s_xy[i] = gxy[i]; s_nn[i] = gnn[i]; s_dp[i] = gdp[i]; }
    __syncthreads();

    const int  loc1   = bx * 1024 + tid;           // always < 19200 (bx<=18: max 18943)
    const int  loc2   = loc1 + 512;
    const bool valid2 = (loc2 < HWSZ);

    const float gxa = (float)(loc1 % IMW), gya = (float)(loc1 / IMW);
    const float gxb = (float)(loc2 % IMW), gyb = (float)(loc2 / IMW);
    const ull gxa2 = pk2(gxa, gxa), gya2 = pk2(gya, gya);
    const ull gxb2 = pk2(gxb, gxb), gyb2 = pk2(gyb, gyb);

    float v1 = 0.f, ds1 = 0.f, v2 = 0.f, ds2 = 0.f;
    #pragma unroll 2
    for (int p = 0; p < npair; p++) {
        const P4 axy = s_xy[p];
        const P4 ann = s_nn[p];
        const float2 dd = s_dp[p];
        // cell 1
        {
            ull dx2  = add2(gxa2, axy.a);
            ull dy2  = add2(gya2, axy.b);
            ull dot2 = fma2(dy2, ann.b, mul2(dx2, ann.a));   // dot' = dot/0.9
            ull d22  = fma2(dy2, dy2, mul2(dx2, dx2));       // d2
            ull q2   = mul2(dot2, dot2);
            float dot0, dot1, q0, q1, e0, e1;
            up2(dot2, dot0, dot1); up2(q2, q0, q1); up2(d22, e0, e1);
            if (dot0 > 0.f && q0 > e0) { v1 += 1.f; ds1 += dd.x; }
            if (dot1 > 0.f && q1 > e1) { v1 += 1.f; ds1 += dd.y; }
        }
        // cell 2
        {
            ull dx2  = add2(gxb2, axy.a);
            ull dy2  = add2(gyb2, axy.b);
            ull dot2 = fma2(dy2, ann.b, mul2(dx2, ann.a));
            ull d22  = fma2(dy2, dy2, mul2(dx2, dx2));
            ull q2   = mul2(dot2, dot2);
            float dot0, dot1, q0, q1, e0, e1;
            up2(dot2, dot0, dot1); up2(q2, q0, q1); up2(d22, e0, e1);
            if (dot0 > 0.f && q0 > e0) { v2 += 1.f; ds2 += dd.x; }
            if (dot1 > 0.f && q1 > e1) { v2 += 1.f; ds2 += dd.y; }
        }
    }
    if (!valid2) v2 = -1.f;                 // sentinel: never wins argmax

    // fold two cells (max count; lower loc on tie -> loc1)
    float bv, bd; int bl;
    if (v2 > v1) { bv = v2; bl = loc2; bd = ds2; }
    else         { bv = v1; bl = loc1; bd = ds1; }

    // warp shuffle argmax (desc v, asc loc on tie)
    #pragma unroll
    for (int off = 16; off > 0; off >>= 1) {
        float ov = __shfl_down_sync(0xFFFFFFFFu, bv, off);
        int   ol = __shfl_down_sync(0xFFFFFFFFu, bl, off);
        float od = __shfl_down_sync(0xFFFFFFFFu, bd, off);
        if (ov > bv || (ov == bv && ol < bl)) { bv = ov; bl = ol; bd = od; }
    }
    if (lane == 0) { s_wv[warp] = bv; s_wl[warp] = bl; s_wd[warp] = bd; }
    __syncthreads();

    if (warp == 0) {
        // lanes 0..15 hold per-warp winners (warp order = ascending loc ranges)
        float wv = (lane < 16) ? s_wv[lane] : -1.f;
        int   wl = (lane < 16) ? s_wl[lane] : 0x7FFFFFFF;
        float wd = (lane < 16) ? s_wd[lane] : 0.f;
        #pragma unroll
        for (int off = 8; off > 0; off >>= 1) {
            float ov = __shfl_down_sync(0xFFFFFFFFu, wv, off);
            int   ol = __shfl_down_sync(0xFFFFFFFFu, wl, off);
            float od = __shfl_down_sync(0xFFFFFFFFu, wd, off);
            if (ov > wv || (ov == wv && ol < wl)) { wv = ov; wl = ol; wd = od; }
        }
        if (lane == 0) {
            g_pv [cls * NBLKC + bx] = wv;
            g_pl [cls * NBLKC + bx] = wl;
            g_pds[cls * NBLKC + bx] = wd;
        }
    }

    // ---- arrival: last block performs final reduction + outputs ----
    __threadfence();
    __syncthreads();
    if (tid == 0) s_old = atomicAdd(&g_ctr, 1u);
    __syncthreads();
    if (s_old != (unsigned)(NBLKC * NCOBJ) - 1u) return;
    __threadfence();

    // warp c handles class c (0..7); class 0 never votes -> zeros path
    const int c = warp;
    if (c < 8) {
        float vmax = 0.f, dsum = 0.f, nv = 0.f;
        int best = 0;
        if (c > 0) {
            const int ci = c - 1;
            float bc = -1.f, bd2 = 0.f; int bl2 = 0x7FFFFFFF;
            if (lane < NBLKC) {
                bc  = g_pv [ci * NBLKC + lane];
                bl2 = g_pl [ci * NBLKC + lane];
                bd2 = g_pds[ci * NBLKC + lane];
            }
            #pragma unroll
            for (int off = 16; off > 0; off >>= 1) {
                float ov = __shfl_down_sync(0xFFFFFFFFu, bc, off);
                int   ol = __shfl_down_sync(0xFFFFFFFFu, bl2, off);
                float od = __shfl_down_sync(0xFFFFFFFFu, bd2, off);
                if (ov > bc || (ov == bc && ol < bl2)) { bc = ov; bl2 = ol; bd2 = od; }
            }
            vmax = bc; best = bl2; dsum = bd2;
            nv = (float)g_cnt[ci];
        }

        if (lane == 0) {
            const float dbar = dsum / fmaxf(vmax, 1.f);
            const float cx = (float)(best % IMW);
            const float cy = (float)(best / IMW);
            const float fx = meta[0], px = meta[2], fy = meta[4], py = meta[5];
            const float e0 = extents[c * 3 + 0];
            const float e1 = extents[c * 3 + 1];
            const float e2 = extents[c * 3 + 2];
            const float diag = sqrtf(e0 * e0 + e1 * e1 + e2 * e2);
            const float safe = fmaxf(dbar, 1e-6f);
            const float bw = diag * fx / safe;
            const float bh = diag * fy / safe;
            const float score = vmax / fmaxf(nv, 1.f);

            float* box = out + c * 7;
            box[0] = 0.f;
            box[1] = (float)c;
            box[2] = cx - bw * 0.5f;
            box[3] = cy - bh * 0.5f;
            box[4] = cx + bw * 0.5f;
            box[5] = cy + bh * 0.5f;
            box[6] = score;

            float* pp = out + 56 + c * 7;
            pp[0] = poses[c * 7 + 0];
            pp[1] = poses[c * 7 + 1];
            pp[2] = poses[c * 7 + 2];
            pp[3] = poses[c * 7 + 3];
            pp[4] = (cx - px) * dbar / fmaxf(fx, 1e-6f);
            pp[5] = (cy - py) * dbar / fmaxf(fy, 1e-6f);
            pp[6] = dbar;
        }
    }
    if (tid == 0) g_ctr = 0;                  // reset for next replay
}

// ============================================================================
extern "C" void kernel_launch(void* const* d_in, const int* in_sizes, int n_in,
                              void* d_out, int out_size)
{
    const int*   labels  = (const int*)d_in[0];
    const int*   masks   = (const int*)d_in[1];
    const float* vp      = (const float*)d_in[2];
    const float* extents = (const float*)d_in[3];
    const float* poses   = (const float*)d_in[4];
    const float* meta    = (const float*)d_in[5];
    float* out = (float*)d_out;

    prep_kernel<<<1, 1024>>>(labels, masks, vp);
    vote_final_kernel<<<dim3(NBLKC, NCOBJ), 512>>>(extents, poses, meta, out);
}

// round 14
// speedup vs baseline: 1.6040x; 1.3945x over previous
#include <cuda_runtime.h>
#include <cuda_bf16.h>
#include <math.h>

#define HWSZ   19200
#define IMW    160
#define NPIX   2400
#define NBLKC  19          // 19 x 1024 cells = 19456 >= 19200
#define NCOBJ  7           // object classes 1..7
#define NPT    5           // pixels per thread in prep (5*512 >= 2400)

typedef unsigned long long ull;

// ---------------- packed f32x2 helpers ----------------
__device__ __forceinline__ ull pk2(float lo, float hi) {
    ull r; asm("mov.b64 %0, {%1, %2};" : "=l"(r) : "f"(lo), "f"(hi)); return r;
}
__device__ __forceinline__ void up2(ull v, float& lo, float& hi) {
    asm("mov.b64 {%0, %1}, %2;" : "=f"(lo), "=f"(hi) : "l"(v));
}
__device__ __forceinline__ ull add2(ull a, ull b) {
    ull r; asm("add.rn.f32x2 %0, %1, %2;" : "=l"(r) : "l"(a), "l"(b)); return r;
}
__device__ __forceinline__ ull mul2(ull a, ull b) {
    ull r; asm("mul.rn.f32x2 %0, %1, %2;" : "=l"(r) : "l"(a), "l"(b)); return r;
}
__device__ __forceinline__ ull fma2(ull a, ull b, ull c) {
    ull r; asm("fma.rn.f32x2 %0, %1, %2, %3;" : "=l"(r) : "l"(a), "l"(b), "l"(c)); return r;
}

// ---------------- global scratch (tiny: partials + counters only) ----------------
__device__ float g_pv[NCOBJ * NBLKC];
__device__ int   g_pl[NCOBJ * NBLKC];
__device__ float g_pds[NCOBJ * NBLKC];
__device__ int   g_cnt[NCOBJ];
__device__ unsigned g_ctr = 0;                   // arrival counter (self-resetting)

struct P4 { ull a, b; };

// ============================================================================
// Single fused kernel: per-block prep (own class) -> vote -> partials;
// last-arriving block does the final per-class reduction + outputs.
// Grid (19, 7), 512 threads.
// ============================================================================
__global__ void __launch_bounds__(512) hough_kernel(const int* __restrict__ labels,
                                                    const int* __restrict__ masks,
                                                    const float* __restrict__ vp,
                                                    const float* __restrict__ extents,
                                                    const float* __restrict__ poses,
                                                    const float* __restrict__ meta,
                                                    float* __restrict__ out)
{
    // pair p: s_xy[p] = (-xs pair, -ys pair); s_nn[p] = (nx' pair, ny' pair)
    __shared__ __align__(16) P4     s_xy[1200];   // 19200 B
    __shared__ __align__(16) P4     s_nn[1200];   // 19200 B
    __shared__ __align__(16) float2 s_dp[1200];   //  9600 B
    __shared__ int s_cnt[NPT][16];
    __shared__ int s_base[NPT][16];
    __shared__ int s_npix;
    __shared__ float s_wv[16];
    __shared__ int   s_wl[16];
    __shared__ float s_wd[16];
    __shared__ unsigned s_old;

    const int cls  = blockIdx.y;            // 0..6 (class cls+1)
    const int bx   = blockIdx.x;            // 0..18
    const int tid  = threadIdx.x;           // 0..511
    const int lane = tid & 31, warp = tid >> 5;
    const int myc  = cls + 1;
    const unsigned below = (1u << lane) - 1u;

    // ================== PREP (this block's class only) ==================
    // batched loads: pixel i = k*512 + tid
    int cv[NPT];
    {
        int labv[NPT], mskv[NPT];
        #pragma unroll
        for (int k = 0; k < NPT; k++) {
            int i = k * 512 + tid;
            labv[k] = (i < NPIX) ? labels[i * 8] : 0;
        }
        #pragma unroll
        for (int k = 0; k < NPT; k++) {
            int i = k * 512 + tid;
            mskv[k] = (i < NPIX) ? masks[i * 8] : 0;
        }
        #pragma unroll
        for (int k = 0; k < NPT; k++)
            cv[k] = (mskv[k] > 0 && labv[k] > 0) ? labv[k] : 0;
    }

    // count pass: per-(iteration, warp) match counts
    #pragma unroll
    for (int k = 0; k < NPT; k++) {
        const unsigned bal = __ballot_sync(0xFFFFFFFFu, cv[k] == myc);
        if (lane == 0) s_cnt[k][warp] = __popc(bal);
    }
    __syncthreads();

    // serial exclusive prefix in (k, warp) order == ascending pixel index
    if (tid == 0) {
        int run = 0;
        #pragma unroll
        for (int k = 0; k < NPT; k++)
            for (int w = 0; w < 16; w++) {
                const int t = s_cnt[k][w];
                s_base[k][w] = run;
                run += t;
            }
        s_npix = run;
    }
    __syncthreads();

    const int npix  = s_npix;
    const int pad   = (npix + 7) & ~7;       // pad to multiple of 8 pixels
    const int npair = pad >> 1;

    // placement pass: matched pixels gather vp, compute, write pair layout
    float* sxyf = (float*)s_xy;
    float* snnf = (float*)s_nn;
    float* sdpf = (float*)s_dp;
    #pragma unroll
    for (int k = 0; k < NPT; k++) {
        const bool m = (cv[k] == myc);
        const unsigned bal = __ballot_sync(0xFFFFFFFFu, m);
        if (m) {
            const int i = k * 512 + tid;
            const int idx = i * 8;
            const float vx = vp[(myc * 3 + 0) * HWSZ + idx];
            const float vy = vp[(myc * 3 + 1) * HWSZ + idx];
            const float vz = vp[(myc * 3 + 2) * HWSZ + idx];
            const float nrm = sqrtf(vx * vx + vy * vy) + 1e-6f;
            const float nxp = (vx / nrm) * (1.0f / 0.9f);
            const float nyp = (vy / nrm) * (1.0f / 0.9f);
            const float xs = (float)(idx % IMW);
            const float ys = (float)(idx / IMW);
            const int slot = s_base[k][warp] + __popc(bal & below);
            const int p = slot >> 1, h = slot & 1;
            sxyf[p * 4 + h]     = -xs;
            sxyf[p * 4 + 2 + h] = -ys;
            snnf[p * 4 + h]     = nxp;
            snnf[p * 4 + 2 + h] = nyp;
            sdpf[p * 2 + h]     = expf(vz);
        }
    }
    // zero the pad region (never-inlier dummies: n'=0 -> dot=0)
    for (int s = npix + tid; s < pad; s += 512) {
        const int p = s >> 1, h = s & 1;
        sxyf[p * 4 + h] = 0.f;  sxyf[p * 4 + 2 + h] = 0.f;
        snnf[p * 4 + h] = 0.f;  snnf[p * 4 + 2 + h] = 0.f;
        sdpf[p * 2 + h] = 0.f;
    }
    if (tid == 0 && bx == 0) g_cnt[cls] = npix;   // publish class pixel count
    __syncthreads();

    // ================== VOTE (identical to R13 champion) ==================
    const int  loc1   = bx * 1024 + tid;          // < 19200 for bx<=18
    const int  loc2   = loc1 + 512;
    const bool valid2 = (loc2 < HWSZ);

    const float gxa = (float)(loc1 % IMW), gya = (float)(loc1 / IMW);
    const float gxb = (float)(loc2 % IMW), gyb = (float)(loc2 / IMW);
    const ull gxa2 = pk2(gxa, gxa), gya2 = pk2(gya, gya);
    const ull gxb2 = pk2(gxb, gxb), gyb2 = pk2(gyb, gyb);

    float v1 = 0.f, ds1 = 0.f, v2 = 0.f, ds2 = 0.f;
    #pragma unroll 2
    for (int p = 0; p < npair; p++) {
        const P4 axy = s_xy[p];
        const P4 ann = s_nn[p];
        const float2 dd = s_dp[p];
        // cell 1
        {
            ull dx2  = add2(gxa2, axy.a);
            ull dy2  = add2(gya2, axy.b);
            ull dot2 = fma2(dy2, ann.b, mul2(dx2, ann.a));   // dot' = dot/0.9
            ull d22  = fma2(dy2, dy2, mul2(dx2, dx2));       // d2
            ull q2   = mul2(dot2, dot2);
            float dot0, dot1, q0, q1, e0, e1;
            up2(dot2, dot0, dot1); up2(q2, q0, q1); up2(d22, e0, e1);
            if (dot0 > 0.f && q0 > e0) { v1 += 1.f; ds1 += dd.x; }
            if (dot1 > 0.f && q1 > e1) { v1 += 1.f; ds1 += dd.y; }
        }
        // cell 2
        {
            ull dx2  = add2(gxb2, axy.a);
            ull dy2  = add2(gyb2, axy.b);
            ull dot2 = fma2(dy2, ann.b, mul2(dx2, ann.a));
            ull d22  = fma2(dy2, dy2, mul2(dx2, dx2));
            ull q2   = mul2(dot2, dot2);
            float dot0, dot1, q0, q1, e0, e1;
            up2(dot2, dot0, dot1); up2(q2, q0, q1); up2(d22, e0, e1);
            if (dot0 > 0.f && q0 > e0) { v2 += 1.f; ds2 += dd.x; }
            if (dot1 > 0.f && q1 > e1) { v2 += 1.f; ds2 += dd.y; }
        }
    }
    if (!valid2) v2 = -1.f;                 // sentinel: never wins argmax

    // fold two cells (max count; lower loc on tie -> loc1)
    float bv, bd; int bl;
    if (v2 > v1) { bv = v2; bl = loc2; bd = ds2; }
    else         { bv = v1; bl = loc1; bd = ds1; }

    // warp shuffle argmax (desc v, asc loc on tie)
    #pragma unroll
    for (int off = 16; off > 0; off >>= 1) {
        float ov = __shfl_down_sync(0xFFFFFFFFu, bv, off);
        int   ol = __shfl_down_sync(0xFFFFFFFFu, bl, off);
        float od = __shfl_down_sync(0xFFFFFFFFu, bd, off);
        if (ov > bv || (ov == bv && ol < bl)) { bv = ov; bl = ol; bd = od; }
    }
    if (lane == 0) { s_wv[warp] = bv; s_wl[warp] = bl; s_wd[warp] = bd; }
    __syncthreads();

    if (warp == 0) {
        float wv = (lane < 16) ? s_wv[lane] : -1.f;
        int   wl = (lane < 16) ? s_wl[lane] : 0x7FFFFFFF;
        float wd = (lane < 16) ? s_wd[lane] : 0.f;
        #pragma unroll
        for (int off = 8; off > 0; off >>= 1) {
            float ov = __shfl_down_sync(0xFFFFFFFFu, wv, off);
            int   ol = __shfl_down_sync(0xFFFFFFFFu, wl, off);
            float od = __shfl_down_sync(0xFFFFFFFFu, wd, off);
            if (ov > wv || (ov == wv && ol < wl)) { wv = ov; wl = ol; wd = od; }
        }
        if (lane == 0) {
            g_pv [cls * NBLKC + bx] = wv;
            g_pl [cls * NBLKC + bx] = wl;
            g_pds[cls * NBLKC + bx] = wd;
        }
    }

    // ---- arrival: last block performs final reduction + outputs ----
    __threadfence();
    __syncthreads();
    if (tid == 0) s_old = atomicAdd(&g_ctr, 1u);
    __syncthreads();
    if (s_old != (unsigned)(NBLKC * NCOBJ) - 1u) return;
    __threadfence();

    // warp c handles class c (0..7); class 0 never votes -> zeros path
    const int c = warp;
    if (c < 8) {
        float vmax = 0.f, dsum = 0.f, nv = 0.f;
        int best = 0;
        if (c > 0) {
            const int ci = c - 1;
            float bc = -1.f, bd2 = 0.f; int bl2 = 0x7FFFFFFF;
            if (lane < NBLKC) {
                bc  = g_pv [ci * NBLKC + lane];
                bl2 = g_pl [ci * NBLKC + lane];
                bd2 = g_pds[ci * NBLKC + lane];
            }
            #pragma unroll
            for (int off = 16; off > 0; off >>= 1) {
                float ov = __shfl_down_sync(0xFFFFFFFFu, bc, off);
                int   ol = __shfl_down_sync(0xFFFFFFFFu, bl2, off);
                float od = __shfl_down_sync(0xFFFFFFFFu, bd2, off);
                if (ov > bc || (ov == bc && ol < bl2)) { bc = ov; bl2 = ol; bd2 = od; }
            }
            vmax = bc; best = bl2; dsum = bd2;
            nv = (float)g_cnt[ci];
        }

        if (lane == 0) {
            const float dbar = dsum / fmaxf(vmax, 1.f);
            const float cx = (float)(best % IMW);
            const float cy = (float)(best / IMW);
            const float fx = meta[0], px = meta[2], fy = meta[4], py = meta[5];
            const float e0 = extents[c * 3 + 0];
            const float e1 = extents[c * 3 + 1];
            const float e2 = extents[c * 3 + 2];
            const float diag = sqrtf(e0 * e0 + e1 * e1 + e2 * e2);
            const float safe = fmaxf(dbar, 1e-6f);
            const float bw = diag * fx / safe;
            const float bh = diag * fy / safe;
            const float score = vmax / fmaxf(nv, 1.f);

            float* box = out + c * 7;
            box[0] = 0.f;
            box[1] = (float)c;
            box[2] = cx - bw * 0.5f;
            box[3] = cy - bh * 0.5f;
            box[4] = cx + bw * 0.5f;
            box[5] = cy + bh * 0.5f;
            box[6] = score;

            float* pp = out + 56 + c * 7;
            pp[0] = poses[c * 7 + 0];
            pp[1] = poses[c * 7 + 1];
            pp[2] = poses[c * 7 + 2];
            pp[3] = poses[c * 7 + 3];
            pp[4] = (cx - px) * dbar / fmaxf(fx, 1e-6f);
            pp[5] = (cy - py) * dbar / fmaxf(fy, 1e-6f);
            pp[6] = dbar;
        }
    }
    if (tid == 0) g_ctr = 0;                  // reset for next replay
}

// ============================================================================
extern "C" void kernel_launch(void* const* d_in, const int* in_sizes, int n_in,
                              void* d_out, int out_size)
{
    const int*   labels  = (const int*)d_in[0];
    const int*   masks   = (const int*)d_in[1];
    const float* vp      = (const float*)d_in[2];
    const float* extents = (const float*)d_in[3];
    const float* poses   = (const float*)d_in[4];
    const float* meta    = (const float*)d_in[5];
    float* out = (float*)d_out;

    hough_kernel<<<dim3(NBLKC, NCOBJ), 512>>>(labels, masks, vp, extents, poses, meta, out);
}